// round 8
// baseline (speedup 1.0000x reference)
#include <cuda_runtime.h>
#include <cuda_bf16.h>
#include <math.h>
#include <stdint.h>

#define BB      2
#define TT      2048
#define DM      2048
#define DI      4096
#define NH      64
#define HD      64
#define DS      64
#define NC      8
#define LL      256
#define DPROJ   16448          // 2*DI + 2*NH*DS + NH = 257*64
#define ROWS    (BB*TT)        // 4096
#define OFF_Z   0
#define OFF_XC  DI             // 4096
#define OFF_B   (2*DI)         // 8192
#define OFF_C   (2*DI + NH*DS) // 12288
#define OFF_DT  (2*DI + 2*NH*DS) // 16384
#define SCALE_F 0.125f         // 64^-0.5
#define RMS_EPS 1.1920929e-07f

// ---------------- scratch (device globals; no allocation allowed) -------------
__device__ float g_proj[(size_t)ROWS * DPROJ];   // 269 MB
__device__ float g_xc  [(size_t)ROWS * DI];      // conv+silu output
__device__ float g_y   [(size_t)ROWS * DI];      // y_intra then +y_inter
__device__ float g_cum [(size_t)BB*NC*NH*LL];    // [b,c,h,l]
__device__ float g_dA  [(size_t)BB*NC*NH];       // chunk decay exp(cum_last)
__device__ float g_dh  [(size_t)BB*NC*NH*HD*DS]; // delta_h [b,c,h,p,n]
__device__ float g_st  [(size_t)BB*NC*NH*HD*DS]; // chunk-begin states

// bf16 hi/lo split operands for the tensor-core GEMMs
__device__ __nv_bfloat16 g_x_h   [(size_t)ROWS * DM];
__device__ __nv_bfloat16 g_x_l   [(size_t)ROWS * DM];
__device__ __nv_bfloat16 g_win_h [(size_t)DPROJ * DM];
__device__ __nv_bfloat16 g_win_l [(size_t)DPROJ * DM];
__device__ __nv_bfloat16 g_wout_h[(size_t)DM * DI];
__device__ __nv_bfloat16 g_wout_l[(size_t)DM * DI];
__device__ __nv_bfloat16 g_yn_h  [(size_t)ROWS * DI];
__device__ __nv_bfloat16 g_yn_l  [(size_t)ROWS * DI];

// ---------------- fp32 -> bf16 hi/lo split (vectorized) ----------------------
__global__ void split_bf16_kernel(const float* __restrict__ src,
                                  __nv_bfloat16* __restrict__ hi,
                                  __nv_bfloat16* __restrict__ lo, int n4)
{
    int i = blockIdx.x * blockDim.x + threadIdx.x;
    if (i >= n4) return;
    float4 v = ((const float4*)src)[i];
    __nv_bfloat16 h0 = __float2bfloat16(v.x);
    __nv_bfloat16 h1 = __float2bfloat16(v.y);
    __nv_bfloat16 h2 = __float2bfloat16(v.z);
    __nv_bfloat16 h3 = __float2bfloat16(v.w);
    __nv_bfloat162 H0; H0.x = h0; H0.y = h1;
    __nv_bfloat162 H1; H1.x = h2; H1.y = h3;
    ((__nv_bfloat162*)hi)[2*i]   = H0;
    ((__nv_bfloat162*)hi)[2*i+1] = H1;
    __nv_bfloat162 L0, L1;
    L0.x = __float2bfloat16(v.x - __bfloat162float(h0));
    L0.y = __float2bfloat16(v.y - __bfloat162float(h1));
    L1.x = __float2bfloat16(v.z - __bfloat162float(h2));
    L1.y = __float2bfloat16(v.w - __bfloat162float(h3));
    ((__nv_bfloat162*)lo)[2*i]   = L0;
    ((__nv_bfloat162*)lo)[2*i+1] = L1;
}

// ---------------- 3x-bf16 tensor-core GEMM (NT): C[m,n]=sum_k A[m,k]B[n,k] ---
// Block 128x64x32; 8 warps as 4(m)x2(n), each warp 32x32 output.
// mma.sync.m16n8k16 row.col f32.bf16.bf16.f32; 3 products: AhBh + AhBl + AlBh.
// Double-buffered smem: register prefetch of k-step k+1 overlaps the MMA burst
// on k; one __syncthreads per iteration. 60 KB smem/CTA -> 2 CTAs/SM.
#define GBM 128
#define GBN 64
#define GBK 32
#define AST 40   // smem row stride (bf16): conflict-free fragment loads

__device__ __forceinline__ void mma_bf16(float* d, const uint32_t* a, const uint32_t* b)
{
    asm volatile(
        "mma.sync.aligned.m16n8k16.row.col.f32.bf16.bf16.f32 "
        "{%0,%1,%2,%3}, {%4,%5,%6,%7}, {%8,%9}, {%0,%1,%2,%3};\n"
        : "+f"(d[0]), "+f"(d[1]), "+f"(d[2]), "+f"(d[3])
        : "r"(a[0]), "r"(a[1]), "r"(a[2]), "r"(a[3]), "r"(b[0]), "r"(b[1]));
}

__global__ __launch_bounds__(256, 2) void gemm_bf16x3(
    const __nv_bfloat16* __restrict__ Ah, const __nv_bfloat16* __restrict__ Al,
    const __nv_bfloat16* __restrict__ Bh, const __nv_bfloat16* __restrict__ Bl,
    float* __restrict__ C, int M, int N, int K)
{
    __shared__ __nv_bfloat16 As[2][2][GBM][AST];   // [buf][hi/lo][m][k]
    __shared__ __nv_bfloat16 Bs[2][2][GBN][AST];   // [buf][hi/lo][n][k]

    const int t    = threadIdx.x;
    const int warp = t >> 5;
    const int lane = t & 31;
    const int g    = lane >> 2;       // fragment group 0..7
    const int tig  = lane & 3;        // thread-in-group
    const int bm   = blockIdx.y * GBM;
    const int bn   = blockIdx.x * GBN;
    const int wm   = (warp & 3) << 5; // warp m offset: 0,32,64,96
    const int wn   = (warp >> 2) << 5;// warp n offset: 0,32

    float acc[2][4][4];
#pragma unroll
    for (int mt = 0; mt < 2; ++mt)
#pragma unroll
        for (int nt = 0; nt < 4; ++nt)
#pragma unroll
            for (int q = 0; q < 4; ++q) acc[mt][nt][q] = 0.f;

    const int lkq = (t & 3) << 3;     // 0,8,16,24 (k offset of 8-elem chunk)
    const int lr  = t >> 2;           // 0..63

    const __nv_bfloat16* Ah0 = Ah + (size_t)(bm + lr     ) * K + lkq;
    const __nv_bfloat16* Ah1 = Ah + (size_t)(bm + lr + 64) * K + lkq;
    const __nv_bfloat16* Al0 = Al + (size_t)(bm + lr     ) * K + lkq;
    const __nv_bfloat16* Al1 = Al + (size_t)(bm + lr + 64) * K + lkq;
    const __nv_bfloat16* Bh0 = Bh + (size_t)(bn + lr     ) * K + lkq;
    const __nv_bfloat16* Bl0 = Bl + (size_t)(bn + lr     ) * K + lkq;

    // prologue: stage k0 = 0 into buffer 0
    {
        *(uint4*)&As[0][0][lr     ][lkq] = *(const uint4*)(Ah0);
        *(uint4*)&As[0][0][lr + 64][lkq] = *(const uint4*)(Ah1);
        *(uint4*)&As[0][1][lr     ][lkq] = *(const uint4*)(Al0);
        *(uint4*)&As[0][1][lr + 64][lkq] = *(const uint4*)(Al1);
        *(uint4*)&Bs[0][0][lr     ][lkq] = *(const uint4*)(Bh0);
        *(uint4*)&Bs[0][1][lr     ][lkq] = *(const uint4*)(Bl0);
    }
    __syncthreads();

    int buf = 0;
    for (int k0 = GBK; k0 <= K; k0 += GBK) {
        // prefetch next k-step into registers (skip past the end)
        uint4 pa0, pa1, pa2, pa3, pb0, pb1;
        const bool more = (k0 < K);
        if (more) {
            pa0 = *(const uint4*)(Ah0 + k0);
            pa1 = *(const uint4*)(Ah1 + k0);
            pa2 = *(const uint4*)(Al0 + k0);
            pa3 = *(const uint4*)(Al1 + k0);
            pb0 = *(const uint4*)(Bh0 + k0);
            pb1 = *(const uint4*)(Bl0 + k0);
        }

        // compute on current buffer
#pragma unroll
        for (int kc = 0; kc < 2; ++kc) {
            const int kb = kc * 16 + tig * 2;
            uint32_t ah[2][4], al[2][4];
#pragma unroll
            for (int mt = 0; mt < 2; ++mt) {
                int r = wm + mt * 16 + g;
                ah[mt][0] = *(const uint32_t*)&As[buf][0][r    ][kb    ];
                ah[mt][1] = *(const uint32_t*)&As[buf][0][r + 8][kb    ];
                ah[mt][2] = *(const uint32_t*)&As[buf][0][r    ][kb + 8];
                ah[mt][3] = *(const uint32_t*)&As[buf][0][r + 8][kb + 8];
                al[mt][0] = *(const uint32_t*)&As[buf][1][r    ][kb    ];
                al[mt][1] = *(const uint32_t*)&As[buf][1][r + 8][kb    ];
                al[mt][2] = *(const uint32_t*)&As[buf][1][r    ][kb + 8];
                al[mt][3] = *(const uint32_t*)&As[buf][1][r + 8][kb + 8];
            }
            uint32_t bh[4][2], bl[4][2];
#pragma unroll
            for (int nt = 0; nt < 4; ++nt) {
                int r = wn + nt * 8 + g;
                bh[nt][0] = *(const uint32_t*)&Bs[buf][0][r][kb    ];
                bh[nt][1] = *(const uint32_t*)&Bs[buf][0][r][kb + 8];
                bl[nt][0] = *(const uint32_t*)&Bs[buf][1][r][kb    ];
                bl[nt][1] = *(const uint32_t*)&Bs[buf][1][r][kb + 8];
            }
#pragma unroll
            for (int mt = 0; mt < 2; ++mt)
#pragma unroll
                for (int nt = 0; nt < 4; ++nt) {
                    mma_bf16(acc[mt][nt], ah[mt], bh[nt]);
                    mma_bf16(acc[mt][nt], ah[mt], bl[nt]);
                    mma_bf16(acc[mt][nt], al[mt], bh[nt]);
                }
        }

        if (more) {
            int nb = buf ^ 1;
            *(uint4*)&As[nb][0][lr     ][lkq] = pa0;
            *(uint4*)&As[nb][0][lr + 64][lkq] = pa1;
            *(uint4*)&As[nb][1][lr     ][lkq] = pa2;
            *(uint4*)&As[nb][1][lr + 64][lkq] = pa3;
            *(uint4*)&Bs[nb][0][lr     ][lkq] = pb0;
            *(uint4*)&Bs[nb][1][lr     ][lkq] = pb1;
            buf = nb;
            __syncthreads();
        }
    }

    // epilogue: c0,c1 -> row g, cols tig*2,+1 ; c2,c3 -> row g+8
#pragma unroll
    for (int mt = 0; mt < 2; ++mt)
#pragma unroll
        for (int nt = 0; nt < 4; ++nt) {
            int m0 = bm + wm + mt * 16 + g;
            int n0 = bn + wn + nt * 8 + tig * 2;
            *(float2*)(C + (size_t)m0 * N + n0)       = make_float2(acc[mt][nt][0], acc[mt][nt][1]);
            *(float2*)(C + (size_t)(m0 + 8) * N + n0) = make_float2(acc[mt][nt][2], acc[mt][nt][3]);
        }
}

// ---------------- depthwise causal conv (k=4) + SiLU -------------------------
__global__ void conv_silu_kernel(const float* __restrict__ conv_w)
{
    int idx = blockIdx.x * blockDim.x + threadIdx.x;   // over ROWS*DI
    if (idx >= ROWS * DI) return;
    int c   = idx & (DI - 1);
    int row = idx >> 12;           // /DI
    int tpos = row & (TT - 1);
    float w0 = conv_w[c*4+0], w1 = conv_w[c*4+1], w2 = conv_w[c*4+2], w3 = conv_w[c*4+3];
    float s = 0.f;
    if (tpos >= 3) s += w0 * g_proj[(size_t)(row-3) * DPROJ + OFF_XC + c];
    if (tpos >= 2) s += w1 * g_proj[(size_t)(row-2) * DPROJ + OFF_XC + c];
    if (tpos >= 1) s += w2 * g_proj[(size_t)(row-1) * DPROJ + OFF_XC + c];
    s += w3 * g_proj[(size_t)row * DPROJ + OFF_XC + c];
    float sig = 1.f / (1.f + __expf(-s));
    g_xc[idx] = s * sig;
}

// ---------------- intra-chunk SSM: one block per (b, chunk, head) ------------
#define SSM_SMEM (size_t)((2*LL*DS + 3*LL) * sizeof(float))
__global__ __launch_bounds__(256, 1) void ssm_intra(
    const float* __restrict__ A_log, const float* __restrict__ dt_bias)
{
    extern __shared__ float sm[];
    float* B_s   = sm;
    float* xd_s  = sm + LL*DS;
    float* cum_s = sm + 2*LL*DS;
    float* dt_s  = cum_s + LL;
    float* w_s   = dt_s + LL;

    const int h = blockIdx.x, c = blockIdx.y, b = blockIdx.z;
    const int i = threadIdx.x;
    const int row0 = b*TT + c*LL;

    // dt + log_dA
    float draw = g_proj[(size_t)(row0 + i) * DPROJ + OFF_DT + h] + dt_bias[h];
    float sp   = (draw > 20.f) ? draw : log1pf(expf(draw));
    float dt   = fminf(fmaxf(sp, 1e-4f), 0.5f);
    float a    = -expf(A_log[h]);
    dt_s[i]  = dt;
    cum_s[i] = a * dt;
    __syncthreads();
    // inclusive prefix (Hillis-Steele)
#pragma unroll
    for (int off = 1; off < LL; off <<= 1) {
        float v = (i >= off) ? cum_s[i - off] : 0.f;
        __syncthreads();
        cum_s[i] += v;
        __syncthreads();
    }
    const float mycum = cum_s[i];

    // cooperative tile loads: B[l][n], xd[l][p] = x[l][p]*dt[l]
    const size_t boff = (size_t)OFF_B + (size_t)h * DS;
    const size_t xoff = (size_t)h * HD;
    for (int idx = i; idx < LL*DS; idx += 256) {
        int l = idx >> 6, n = idx & 63;
        B_s[idx]  = g_proj[(size_t)(row0 + l) * DPROJ + boff + n];
        xd_s[idx] = g_xc[(size_t)(row0 + l) * DI + xoff + n] * dt_s[l];
    }
    // C row -> registers
    float Cr[DS];
    {
        const float* crow = g_proj + (size_t)(row0 + i) * DPROJ + OFF_C + h * DS;
#pragma unroll
        for (int n = 0; n < DS; n += 4) {
            float4 v = *(const float4*)(crow + n);
            Cr[n] = v.x; Cr[n+1] = v.y; Cr[n+2] = v.z; Cr[n+3] = v.w;
        }
    }
    __syncthreads();

    float acc[HD];
#pragma unroll
    for (int p = 0; p < HD; ++p) acc[p] = 0.f;

    const int imax = i | 31;   // warp-uniform bound
    for (int j = 0; j <= imax; ++j) {
        float s = 0.f;
#pragma unroll
        for (int n = 0; n < DS; n += 4) {
            float4 bv = *(const float4*)&B_s[j*DS + n];
            s += Cr[n]*bv.x + Cr[n+1]*bv.y + Cr[n+2]*bv.z + Cr[n+3]*bv.w;
        }
        float w    = __expf(mycum - cum_s[j]) * SCALE_F;
        float coef = (j <= i) ? s * w : 0.f;
#pragma unroll
        for (int p = 0; p < HD; p += 4) {
            float4 xv = *(const float4*)&xd_s[j*HD + p];
            acc[p]   += coef*xv.x; acc[p+1] += coef*xv.y;
            acc[p+2] += coef*xv.z; acc[p+3] += coef*xv.w;
        }
    }

    // store y_intra
    float* yrow = g_y + (size_t)(row0 + i) * DI + h * HD;
#pragma unroll
    for (int p = 0; p < HD; p += 4)
        *(float4*)(yrow + p) = make_float4(acc[p], acc[p+1], acc[p+2], acc[p+3]);

    // store cum [b,c,h,l]
    const size_t bch = ((size_t)(b*NC + c) * NH + h);
    g_cum[bch * LL + i] = mycum;
    const float cl = cum_s[LL-1];
    if (i == 0) g_dA[bch] = __expf(cl);
    w_s[i] = __expf(cl - mycum);     // decay_to_end
    __syncthreads();

    // delta_h[p,n] = sum_l w_l * xd[l,p] * B[l,n]
    const int p  = i >> 2;
    const int n0 = (i & 3) << 4;
    float dacc[16];
#pragma unroll
    for (int q = 0; q < 16; ++q) dacc[q] = 0.f;
    for (int l = 0; l < LL; ++l) {
        float tmp = w_s[l] * xd_s[l*HD + p];
#pragma unroll
        for (int q = 0; q < 16; q += 4) {
            float4 bv = *(const float4*)&B_s[l*DS + n0 + q];
            dacc[q]   += tmp*bv.x; dacc[q+1] += tmp*bv.y;
            dacc[q+2] += tmp*bv.z; dacc[q+3] += tmp*bv.w;
        }
    }
    float* dst = g_dh + (bch * HD + p) * DS + n0;
#pragma unroll
    for (int q = 0; q < 16; q += 4)
        *(float4*)(dst + q) = make_float4(dacc[q], dacc[q+1], dacc[q+2], dacc[q+3]);
}

// ---------------- sequential inter-chunk scan (8 chunks) ---------------------
__global__ void scan_chunks()
{
    const int bh = blockIdx.x;            // 0..127
    const int b  = bh >> 6, h = bh & 63;
    const int base = threadIdx.x * 16;    // 256 threads * 16 = 4096 elems
    float st[16];
#pragma unroll
    for (int q = 0; q < 16; ++q) st[q] = 0.f;
    for (int c = 0; c < NC; ++c) {
        const size_t bch = ((size_t)(b*NC + c) * NH + h);
        const size_t off = bch * (HD*DS) + base;
        const float da = g_dA[bch];
#pragma unroll
        for (int q = 0; q < 16; q += 4) {
            float4 d = *(const float4*)(g_dh + off + q);
            *(float4*)(g_st + off + q) = make_float4(st[q], st[q+1], st[q+2], st[q+3]);
            st[q]   = da*st[q]   + d.x;  st[q+1] = da*st[q+1] + d.y;
            st[q+2] = da*st[q+2] + d.z;  st[q+3] = da*st[q+3] + d.w;
        }
    }
}

// ---------------- y_inter: y += exp(cum_i)*SCALE * (C_i . state[p,:]) --------
__global__ __launch_bounds__(256) void y_inter_kernel()
{
    __shared__ float st_s[DS*HD];   // [n][p]
    const int h = blockIdx.x, c = blockIdx.y, b = blockIdx.z;
    const int i = threadIdx.x;
    const int row0 = b*TT + c*LL;
    const size_t bch = ((size_t)(b*NC + c) * NH + h);
    const size_t soff = bch * (HD*DS);
    for (int idx = i; idx < HD*DS; idx += 256) {
        int p = idx >> 6, n = idx & 63;
        st_s[n*HD + p] = g_st[soff + idx];   // transpose [p][n] -> [n][p]
    }
    float Cr[DS];
    {
        const float* crow = g_proj + (size_t)(row0 + i) * DPROJ + OFF_C + h * DS;
#pragma unroll
        for (int n = 0; n < DS; n += 4) {
            float4 v = *(const float4*)(crow + n);
            Cr[n] = v.x; Cr[n+1] = v.y; Cr[n+2] = v.z; Cr[n+3] = v.w;
        }
    }
    const float ei = __expf(g_cum[bch * LL + i]) * SCALE_F;
    __syncthreads();

    float acc[HD];
#pragma unroll
    for (int p = 0; p < HD; ++p) acc[p] = 0.f;
#pragma unroll 4
    for (int n = 0; n < DS; ++n) {
        float cn = Cr[n];
#pragma unroll
        for (int p = 0; p < HD; p += 4) {
            float4 sv = *(const float4*)&st_s[n*HD + p];
            acc[p]   += cn*sv.x; acc[p+1] += cn*sv.y;
            acc[p+2] += cn*sv.z; acc[p+3] += cn*sv.w;
        }
    }
    float* yrow = g_y + (size_t)(row0 + i) * DI + h * HD;
#pragma unroll
    for (int p = 0; p < HD; p += 4) {
        float4 v = *(const float4*)(yrow + p);
        v.x += ei*acc[p]; v.y += ei*acc[p+1]; v.z += ei*acc[p+2]; v.w += ei*acc[p+3];
        *(float4*)(yrow + p) = v;
    }
}

// ---------------- RMS norm + SiLU(z) gate -> bf16 hi/lo split ----------------
__global__ void rms_gate_kernel()
{
    const int row = blockIdx.x;
    const int t = threadIdx.x;    // 256
    __shared__ float red[256];
    const float* yr = g_y + (size_t)row * DI;
    float ss = 0.f;
    for (int idx = t; idx < DI; idx += 256) { float v = yr[idx]; ss += v*v; }
    red[t] = ss;
    __syncthreads();
    for (int s = 128; s > 0; s >>= 1) {
        if (t < s) red[t] += red[t + s];
        __syncthreads();
    }
    const float r = rsqrtf(red[0] * (1.f/DI) + RMS_EPS);
    const float* zr = g_proj + (size_t)row * DPROJ + OFF_Z;
    for (int idx = t; idx < DI; idx += 256) {
        float v = yr[idx] * r;
        float z = zr[idx];
        float sig = 1.f / (1.f + __expf(-z));
        float o = v * z * sig;
        __nv_bfloat16 hh = __float2bfloat16(o);
        g_yn_h[(size_t)row * DI + idx] = hh;
        g_yn_l[(size_t)row * DI + idx] = __float2bfloat16(o - __bfloat162float(hh));
    }
}

// ---------------- launch -----------------------------------------------------
extern "C" void kernel_launch(void* const* d_in, const int* in_sizes, int n_in,
                              void* d_out, int out_size)
{
    const float* x      = (const float*)d_in[0];
    const float* win    = (const float*)d_in[1];
    const float* convw  = (const float*)d_in[2];
    const float* alog   = (const float*)d_in[3];
    const float* dtb    = (const float*)d_in[4];
    const float* wout   = (const float*)d_in[5];
    float* out = (float*)d_out;

    void *p_proj, *p_xh, *p_xl, *p_winh, *p_winl, *p_wouth, *p_woutl, *p_ynh, *p_ynl;
    cudaGetSymbolAddress(&p_proj,  g_proj);
    cudaGetSymbolAddress(&p_xh,    g_x_h);
    cudaGetSymbolAddress(&p_xl,    g_x_l);
    cudaGetSymbolAddress(&p_winh,  g_win_h);
    cudaGetSymbolAddress(&p_winl,  g_win_l);
    cudaGetSymbolAddress(&p_wouth, g_wout_h);
    cudaGetSymbolAddress(&p_woutl, g_wout_l);
    cudaGetSymbolAddress(&p_ynh,   g_yn_h);
    cudaGetSymbolAddress(&p_ynl,   g_yn_l);

    cudaFuncSetAttribute(ssm_intra, cudaFuncAttributeMaxDynamicSharedMemorySize,
                         (int)SSM_SMEM);

    // 0) split fp32 operands into bf16 hi/lo
    {
        int n4x = (ROWS * DM) / 4;                 // 2,097,152
        split_bf16_kernel<<<(n4x + 255) / 256, 256>>>(
            x, (__nv_bfloat16*)p_xh, (__nv_bfloat16*)p_xl, n4x);
        int n4w = (DPROJ * DM) / 4;                // 8,421,376
        split_bf16_kernel<<<(n4w + 255) / 256, 256>>>(
            win, (__nv_bfloat16*)p_winh, (__nv_bfloat16*)p_winl, n4w);
        int n4o = (DM * DI) / 4;                   // 2,097,152
        split_bf16_kernel<<<(n4o + 255) / 256, 256>>>(
            wout, (__nv_bfloat16*)p_wouth, (__nv_bfloat16*)p_woutl, n4o);
    }

    // 1) in_proj: proj[4096,16448] = x @ win^T   (DPROJ = 257*64 exact tiles)
    {
        dim3 grid(DPROJ / GBN, ROWS / GBM);        // (257, 32)
        gemm_bf16x3<<<grid, 256>>>(
            (const __nv_bfloat16*)p_xh,  (const __nv_bfloat16*)p_xl,
            (const __nv_bfloat16*)p_winh,(const __nv_bfloat16*)p_winl,
            (float*)p_proj, ROWS, DPROJ, DM);
    }
    // 2) conv + silu
    conv_silu_kernel<<<(ROWS*DI)/256, 256>>>(convw);
    // 3) intra-chunk SSM
    {
        dim3 grid(NH, NC, BB);
        ssm_intra<<<grid, 256, SSM_SMEM>>>(alog, dtb);
    }
    // 4) inter-chunk scan
    scan_chunks<<<BB*NH, 256>>>();
    // 5) y_inter accumulate
    {
        dim3 grid(NH, NC, BB);
        y_inter_kernel<<<grid, 256>>>();
    }
    // 6) RMS norm + gate -> yn hi/lo
    rms_gate_kernel<<<ROWS, 256>>>();
    // 7) out_proj: out[4096,2048] = yn @ wout^T
    {
        dim3 grid(DM / GBN, ROWS / GBM);           // (32, 32)
        gemm_bf16x3<<<grid, 256>>>(
            (const __nv_bfloat16*)p_ynh, (const __nv_bfloat16*)p_ynl,
            (const __nv_bfloat16*)p_wouth,(const __nv_bfloat16*)p_woutl,
            out, ROWS, DM, DI);
    }
}

// round 9
// speedup vs baseline: 1.2341x; 1.2341x over previous
#include <cuda_runtime.h>
#include <cuda_bf16.h>
#include <math.h>
#include <stdint.h>

#define BB      2
#define TT      2048
#define DM      2048
#define DI      4096
#define NH      64
#define HD      64
#define DS      64
#define NC      8
#define LL      256
#define DPROJ   16448          // 2*DI + 2*NH*DS + NH
#define PSTR    16512          // padded proj row stride = 129*128
#define ROWS    (BB*TT)        // 4096
#define OFF_Z   0
#define OFF_XC  DI             // 4096
#define OFF_B   (2*DI)         // 8192
#define OFF_C   (2*DI + NH*DS) // 12288
#define OFF_DT  (2*DI + 2*NH*DS) // 16384
#define SCALE_F 0.125f         // 64^-0.5
#define RMS_EPS 1.1920929e-07f

// ---------------- scratch (device globals; no allocation allowed) -------------
__device__ float g_proj[(size_t)ROWS * PSTR];    // padded stride
__device__ float g_xc  [(size_t)ROWS * DI];
__device__ float g_y   [(size_t)ROWS * DI];
__device__ float g_cum [(size_t)BB*NC*NH*LL];
__device__ float g_dA  [(size_t)BB*NC*NH];
__device__ float g_dh  [(size_t)BB*NC*NH*HD*DS];
__device__ float g_st  [(size_t)BB*NC*NH*HD*DS];

// bf16 hi/lo split operands (win padded to PSTR rows; tail rows stay zero-init)
__device__ __nv_bfloat16 g_x_h   [(size_t)ROWS * DM];
__device__ __nv_bfloat16 g_x_l   [(size_t)ROWS * DM];
__device__ __nv_bfloat16 g_win_h [(size_t)PSTR * DM];
__device__ __nv_bfloat16 g_win_l [(size_t)PSTR * DM];
__device__ __nv_bfloat16 g_wout_h[(size_t)DM * DI];
__device__ __nv_bfloat16 g_wout_l[(size_t)DM * DI];
__device__ __nv_bfloat16 g_yn_h  [(size_t)ROWS * DI];
__device__ __nv_bfloat16 g_yn_l  [(size_t)ROWS * DI];

// ---------------- fp32 -> bf16 hi/lo split (vectorized) ----------------------
__global__ void split_bf16_kernel(const float* __restrict__ src,
                                  __nv_bfloat16* __restrict__ hi,
                                  __nv_bfloat16* __restrict__ lo, int n4)
{
    int i = blockIdx.x * blockDim.x + threadIdx.x;
    if (i >= n4) return;
    float4 v = ((const float4*)src)[i];
    __nv_bfloat16 h0 = __float2bfloat16(v.x);
    __nv_bfloat16 h1 = __float2bfloat16(v.y);
    __nv_bfloat16 h2 = __float2bfloat16(v.z);
    __nv_bfloat16 h3 = __float2bfloat16(v.w);
    __nv_bfloat162 H0; H0.x = h0; H0.y = h1;
    __nv_bfloat162 H1; H1.x = h2; H1.y = h3;
    ((__nv_bfloat162*)hi)[2*i]   = H0;
    ((__nv_bfloat162*)hi)[2*i+1] = H1;
    __nv_bfloat162 L0, L1;
    L0.x = __float2bfloat16(v.x - __bfloat162float(h0));
    L0.y = __float2bfloat16(v.y - __bfloat162float(h1));
    L1.x = __float2bfloat16(v.z - __bfloat162float(h2));
    L1.y = __float2bfloat16(v.w - __bfloat162float(h3));
    ((__nv_bfloat162*)lo)[2*i]   = L0;
    ((__nv_bfloat162*)lo)[2*i+1] = L1;
}

// ---------------- 3x-bf16 tensor-core GEMM (NT) ------------------------------
// Block 128x128x32, 8 warps 4(m)x2(n), warp tile 32x64.
// ldmatrix.x4 fragment loads; cp.async double-buffered staging.
#define GBM 128
#define GBN 128
#define GBK 32
#define ASTB 80                    // smem row stride bytes (40 bf16)
#define TILE_SLOT (128*ASTB)       // bytes per [buf][type] slab = 10240
#define AS_BYTES (4*TILE_SLOT)     // A region: 2 buf x 2 type = 40960
#define GSMEM (2*AS_BYTES)         // 81920 total

#define LDSM_X4(r, addr) \
    asm volatile("ldmatrix.sync.aligned.m8n8.x4.shared.b16 {%0,%1,%2,%3}, [%4];" \
        : "=r"((r)[0]),"=r"((r)[1]),"=r"((r)[2]),"=r"((r)[3]) : "r"(addr))
#define CP_ASYNC16(dst, src) \
    asm volatile("cp.async.cg.shared.global [%0], [%1], 16;" :: "r"(dst), "l"(src))
#define CP_COMMIT() asm volatile("cp.async.commit_group;")
#define CP_WAIT0()  asm volatile("cp.async.wait_group 0;")

__device__ __forceinline__ void mma_bf16(float* d, const uint32_t* a, const uint32_t* b)
{
    asm volatile(
        "mma.sync.aligned.m16n8k16.row.col.f32.bf16.bf16.f32 "
        "{%0,%1,%2,%3}, {%4,%5,%6,%7}, {%8,%9}, {%0,%1,%2,%3};\n"
        : "+f"(d[0]), "+f"(d[1]), "+f"(d[2]), "+f"(d[3])
        : "r"(a[0]), "r"(a[1]), "r"(a[2]), "r"(a[3]), "r"(b[0]), "r"(b[1]));
}

__global__ __launch_bounds__(256, 2) void gemm_bf16x3(
    const __nv_bfloat16* __restrict__ Ah, const __nv_bfloat16* __restrict__ Al,
    const __nv_bfloat16* __restrict__ Bh, const __nv_bfloat16* __restrict__ Bl,
    float* __restrict__ C, int M, int N, int K)
{
    extern __shared__ char gsm[];
    const uint32_t asBase = (uint32_t)__cvta_generic_to_shared(gsm);
    const uint32_t bsBase = asBase + AS_BYTES;

    const int t    = threadIdx.x;
    const int warp = t >> 5;
    const int lane = t & 31;
    const int g    = lane >> 2;
    const int tig  = lane & 3;
    const int bm   = blockIdx.y * GBM;
    const int bn   = blockIdx.x * GBN;
    const int wm   = (warp & 3) << 5;   // 0,32,64,96
    const int wn   = (warp >> 2) << 6;  // 0,64

    float acc[2][8][4];
#pragma unroll
    for (int mt = 0; mt < 2; ++mt)
#pragma unroll
        for (int nt = 0; nt < 8; ++nt)
#pragma unroll
            for (int q = 0; q < 4; ++q) acc[mt][nt][q] = 0.f;

    const int lr  = t >> 2;          // 0..63
    const int lkq = (t & 3) << 3;    // 0,8,16,24 elems
    const uint32_t lkb = (uint32_t)lkq * 2;  // bytes

    const __nv_bfloat16* pAh0 = Ah + (size_t)(bm + lr     ) * K + lkq;
    const __nv_bfloat16* pAh1 = Ah + (size_t)(bm + lr + 64) * K + lkq;
    const __nv_bfloat16* pAl0 = Al + (size_t)(bm + lr     ) * K + lkq;
    const __nv_bfloat16* pAl1 = Al + (size_t)(bm + lr + 64) * K + lkq;
    const __nv_bfloat16* pBh0 = Bh + (size_t)(bn + lr     ) * K + lkq;
    const __nv_bfloat16* pBh1 = Bh + (size_t)(bn + lr + 64) * K + lkq;
    const __nv_bfloat16* pBl0 = Bl + (size_t)(bn + lr     ) * K + lkq;
    const __nv_bfloat16* pBl1 = Bl + (size_t)(bn + lr + 64) * K + lkq;

    // per-lane ldmatrix address offsets (bytes)
    // A tiles: t0=(r0,k0) t1=(r0+8,k0) t2=(r0,k0+8) t3=(r0+8,k0+8)
    const uint32_t offA = (uint32_t)(((lane & 7) + ((lane >> 3) & 1) * 8) * ASTB
                                     + ((lane >> 4) & 1) * 16);
    // B tiles: t0=(n0,k0) t1=(n0,k0+8) t2=(n0+8,k0) t3=(n0+8,k0+8)
    const uint32_t offB = (uint32_t)(((lane & 7) + ((lane >> 4) & 1) * 8) * ASTB
                                     + ((lane >> 3) & 1) * 16);

#define STAGE(b, k0) do {                                                        \
    uint32_t ab = asBase + (uint32_t)(b) * 2 * TILE_SLOT;                        \
    uint32_t bb = bsBase + (uint32_t)(b) * 2 * TILE_SLOT;                        \
    CP_ASYNC16(ab + (uint32_t)lr*ASTB + lkb,                pAh0 + (k0));        \
    CP_ASYNC16(ab + (uint32_t)(lr+64)*ASTB + lkb,           pAh1 + (k0));        \
    CP_ASYNC16(ab + TILE_SLOT + (uint32_t)lr*ASTB + lkb,    pAl0 + (k0));        \
    CP_ASYNC16(ab + TILE_SLOT + (uint32_t)(lr+64)*ASTB + lkb, pAl1 + (k0));      \
    CP_ASYNC16(bb + (uint32_t)lr*ASTB + lkb,                pBh0 + (k0));        \
    CP_ASYNC16(bb + (uint32_t)(lr+64)*ASTB + lkb,           pBh1 + (k0));        \
    CP_ASYNC16(bb + TILE_SLOT + (uint32_t)lr*ASTB + lkb,    pBl0 + (k0));        \
    CP_ASYNC16(bb + TILE_SLOT + (uint32_t)(lr+64)*ASTB + lkb, pBl1 + (k0));      \
} while (0)

    STAGE(0, 0);
    CP_COMMIT();
    CP_WAIT0();
    __syncthreads();

    int buf = 0;
    for (int k0 = GBK; k0 <= K; k0 += GBK) {
        const bool more = (k0 < K);
        if (more) { STAGE(buf ^ 1, k0); CP_COMMIT(); }

        const uint32_t abuf = asBase + (uint32_t)buf * 2 * TILE_SLOT;
        const uint32_t bbuf = bsBase + (uint32_t)buf * 2 * TILE_SLOT;
#pragma unroll
        for (int kc = 0; kc < 2; ++kc) {
            const uint32_t kb = (uint32_t)kc * 32;   // bytes
            uint32_t ah[2][4], al[2][4];
#pragma unroll
            for (int mt = 0; mt < 2; ++mt) {
                uint32_t rbase = (uint32_t)(wm + mt * 16) * ASTB + kb;
                LDSM_X4(ah[mt], abuf + rbase + offA);
                LDSM_X4(al[mt], abuf + TILE_SLOT + rbase + offA);
            }
#pragma unroll
            for (int ntp = 0; ntp < 4; ++ntp) {
                uint32_t bh2[4], bl2[4];
                uint32_t nbase = (uint32_t)(wn + ntp * 16) * ASTB + kb;
                LDSM_X4(bh2, bbuf + nbase + offB);
                LDSM_X4(bl2, bbuf + TILE_SLOT + nbase + offB);
#pragma unroll
                for (int j = 0; j < 2; ++j) {
                    const int nt = ntp * 2 + j;
#pragma unroll
                    for (int mt = 0; mt < 2; ++mt) {
                        mma_bf16(acc[mt][nt], ah[mt], &bh2[2*j]);
                        mma_bf16(acc[mt][nt], ah[mt], &bl2[2*j]);
                        mma_bf16(acc[mt][nt], al[mt], &bh2[2*j]);
                    }
                }
            }
        }

        if (more) {
            CP_WAIT0();
            __syncthreads();
            buf ^= 1;
        }
    }

#pragma unroll
    for (int mt = 0; mt < 2; ++mt)
#pragma unroll
        for (int nt = 0; nt < 8; ++nt) {
            int m0 = bm + wm + mt * 16 + g;
            int n0 = bn + wn + nt * 8 + tig * 2;
            *(float2*)(C + (size_t)m0 * N + n0)       = make_float2(acc[mt][nt][0], acc[mt][nt][1]);
            *(float2*)(C + (size_t)(m0 + 8) * N + n0) = make_float2(acc[mt][nt][2], acc[mt][nt][3]);
        }
#undef STAGE
}

// ---------------- depthwise causal conv (k=4) + SiLU -------------------------
__global__ void conv_silu_kernel(const float* __restrict__ conv_w)
{
    int idx = blockIdx.x * blockDim.x + threadIdx.x;
    if (idx >= ROWS * DI) return;
    int c   = idx & (DI - 1);
    int row = idx >> 12;
    int tpos = row & (TT - 1);
    float w0 = conv_w[c*4+0], w1 = conv_w[c*4+1], w2 = conv_w[c*4+2], w3 = conv_w[c*4+3];
    float s = 0.f;
    if (tpos >= 3) s += w0 * g_proj[(size_t)(row-3) * PSTR + OFF_XC + c];
    if (tpos >= 2) s += w1 * g_proj[(size_t)(row-2) * PSTR + OFF_XC + c];
    if (tpos >= 1) s += w2 * g_proj[(size_t)(row-1) * PSTR + OFF_XC + c];
    s += w3 * g_proj[(size_t)row * PSTR + OFF_XC + c];
    float sig = 1.f / (1.f + __expf(-s));
    g_xc[idx] = s * sig;
}

// ---------------- intra-chunk SSM: one block per (b, chunk, head) ------------
#define SSM_SMEM (size_t)((2*LL*DS + 3*LL) * sizeof(float))
__global__ __launch_bounds__(256, 1) void ssm_intra(
    const float* __restrict__ A_log, const float* __restrict__ dt_bias)
{
    extern __shared__ float sm[];
    float* B_s   = sm;
    float* xd_s  = sm + LL*DS;
    float* cum_s = sm + 2*LL*DS;
    float* dt_s  = cum_s + LL;
    float* w_s   = dt_s + LL;

    const int h = blockIdx.x, c = blockIdx.y, b = blockIdx.z;
    const int i = threadIdx.x;
    const int row0 = b*TT + c*LL;

    float draw = g_proj[(size_t)(row0 + i) * PSTR + OFF_DT + h] + dt_bias[h];
    float sp   = (draw > 20.f) ? draw : log1pf(expf(draw));
    float dt   = fminf(fmaxf(sp, 1e-4f), 0.5f);
    float a    = -expf(A_log[h]);
    dt_s[i]  = dt;
    cum_s[i] = a * dt;
    __syncthreads();
#pragma unroll
    for (int off = 1; off < LL; off <<= 1) {
        float v = (i >= off) ? cum_s[i - off] : 0.f;
        __syncthreads();
        cum_s[i] += v;
        __syncthreads();
    }
    const float mycum = cum_s[i];

    const size_t boff = (size_t)OFF_B + (size_t)h * DS;
    const size_t xoff = (size_t)h * HD;
    for (int idx = i; idx < LL*DS; idx += 256) {
        int l = idx >> 6, n = idx & 63;
        B_s[idx]  = g_proj[(size_t)(row0 + l) * PSTR + boff + n];
        xd_s[idx] = g_xc[(size_t)(row0 + l) * DI + xoff + n] * dt_s[l];
    }
    float Cr[DS];
    {
        const float* crow = g_proj + (size_t)(row0 + i) * PSTR + OFF_C + h * DS;
#pragma unroll
        for (int n = 0; n < DS; n += 4) {
            float4 v = *(const float4*)(crow + n);
            Cr[n] = v.x; Cr[n+1] = v.y; Cr[n+2] = v.z; Cr[n+3] = v.w;
        }
    }
    __syncthreads();

    float acc[HD];
#pragma unroll
    for (int p = 0; p < HD; ++p) acc[p] = 0.f;

    const int imax = i | 31;
    for (int j = 0; j <= imax; ++j) {
        float s = 0.f;
#pragma unroll
        for (int n = 0; n < DS; n += 4) {
            float4 bv = *(const float4*)&B_s[j*DS + n];
            s += Cr[n]*bv.x + Cr[n+1]*bv.y + Cr[n+2]*bv.z + Cr[n+3]*bv.w;
        }
        float w    = __expf(mycum - cum_s[j]) * SCALE_F;
        float coef = (j <= i) ? s * w : 0.f;
#pragma unroll
        for (int p = 0; p < HD; p += 4) {
            float4 xv = *(const float4*)&xd_s[j*HD + p];
            acc[p]   += coef*xv.x; acc[p+1] += coef*xv.y;
            acc[p+2] += coef*xv.z; acc[p+3] += coef*xv.w;
        }
    }

    float* yrow = g_y + (size_t)(row0 + i) * DI + h * HD;
#pragma unroll
    for (int p = 0; p < HD; p += 4)
        *(float4*)(yrow + p) = make_float4(acc[p], acc[p+1], acc[p+2], acc[p+3]);

    const size_t bch = ((size_t)(b*NC + c) * NH + h);
    g_cum[bch * LL + i] = mycum;
    const float cl = cum_s[LL-1];
    if (i == 0) g_dA[bch] = __expf(cl);
    w_s[i] = __expf(cl - mycum);
    __syncthreads();

    const int p  = i >> 2;
    const int n0 = (i & 3) << 4;
    float dacc[16];
#pragma unroll
    for (int q = 0; q < 16; ++q) dacc[q] = 0.f;
    for (int l = 0; l < LL; ++l) {
        float tmp = w_s[l] * xd_s[l*HD + p];
#pragma unroll
        for (int q = 0; q < 16; q += 4) {
            float4 bv = *(const float4*)&B_s[l*DS + n0 + q];
            dacc[q]   += tmp*bv.x; dacc[q+1] += tmp*bv.y;
            dacc[q+2] += tmp*bv.z; dacc[q+3] += tmp*bv.w;
        }
    }
    float* dst = g_dh + (bch * HD + p) * DS + n0;
#pragma unroll
    for (int q = 0; q < 16; q += 4)
        *(float4*)(dst + q) = make_float4(dacc[q], dacc[q+1], dacc[q+2], dacc[q+3]);
}

// ---------------- sequential inter-chunk scan (8 chunks) ---------------------
__global__ void scan_chunks()
{
    const int bh = blockIdx.x;
    const int b  = bh >> 6, h = bh & 63;
    const int base = threadIdx.x * 16;
    float st[16];
#pragma unroll
    for (int q = 0; q < 16; ++q) st[q] = 0.f;
    for (int c = 0; c < NC; ++c) {
        const size_t bch = ((size_t)(b*NC + c) * NH + h);
        const size_t off = bch * (HD*DS) + base;
        const float da = g_dA[bch];
#pragma unroll
        for (int q = 0; q < 16; q += 4) {
            float4 d = *(const float4*)(g_dh + off + q);
            *(float4*)(g_st + off + q) = make_float4(st[q], st[q+1], st[q+2], st[q+3]);
            st[q]   = da*st[q]   + d.x;  st[q+1] = da*st[q+1] + d.y;
            st[q+2] = da*st[q+2] + d.z;  st[q+3] = da*st[q+3] + d.w;
        }
    }
}

// ---------------- y_inter ----------------------------------------------------
__global__ __launch_bounds__(256) void y_inter_kernel()
{
    __shared__ float st_s[DS*HD];
    const int h = blockIdx.x, c = blockIdx.y, b = blockIdx.z;
    const int i = threadIdx.x;
    const int row0 = b*TT + c*LL;
    const size_t bch = ((size_t)(b*NC + c) * NH + h);
    const size_t soff = bch * (HD*DS);
    for (int idx = i; idx < HD*DS; idx += 256) {
        int p = idx >> 6, n = idx & 63;
        st_s[n*HD + p] = g_st[soff + idx];
    }
    float Cr[DS];
    {
        const float* crow = g_proj + (size_t)(row0 + i) * PSTR + OFF_C + h * DS;
#pragma unroll
        for (int n = 0; n < DS; n += 4) {
            float4 v = *(const float4*)(crow + n);
            Cr[n] = v.x; Cr[n+1] = v.y; Cr[n+2] = v.z; Cr[n+3] = v.w;
        }
    }
    const float ei = __expf(g_cum[bch * LL + i]) * SCALE_F;
    __syncthreads();

    float acc[HD];
#pragma unroll
    for (int p = 0; p < HD; ++p) acc[p] = 0.f;
#pragma unroll 4
    for (int n = 0; n < DS; ++n) {
        float cn = Cr[n];
#pragma unroll
        for (int p = 0; p < HD; p += 4) {
            float4 sv = *(const float4*)&st_s[n*HD + p];
            acc[p]   += cn*sv.x; acc[p+1] += cn*sv.y;
            acc[p+2] += cn*sv.z; acc[p+3] += cn*sv.w;
        }
    }
    float* yrow = g_y + (size_t)(row0 + i) * DI + h * HD;
#pragma unroll
    for (int p = 0; p < HD; p += 4) {
        float4 v = *(const float4*)(yrow + p);
        v.x += ei*acc[p]; v.y += ei*acc[p+1]; v.z += ei*acc[p+2]; v.w += ei*acc[p+3];
        *(float4*)(yrow + p) = v;
    }
}

// ---------------- RMS norm + SiLU(z) gate -> bf16 hi/lo split ----------------
__global__ void rms_gate_kernel()
{
    const int row = blockIdx.x;
    const int t = threadIdx.x;
    __shared__ float red[256];
    const float* yr = g_y + (size_t)row * DI;
    float ss = 0.f;
    for (int idx = t; idx < DI; idx += 256) { float v = yr[idx]; ss += v*v; }
    red[t] = ss;
    __syncthreads();
    for (int s = 128; s > 0; s >>= 1) {
        if (t < s) red[t] += red[t + s];
        __syncthreads();
    }
    const float r = rsqrtf(red[0] * (1.f/DI) + RMS_EPS);
    const float* zr = g_proj + (size_t)row * PSTR + OFF_Z;
    for (int idx = t; idx < DI; idx += 256) {
        float v = yr[idx] * r;
        float z = zr[idx];
        float sig = 1.f / (1.f + __expf(-z));
        float o = v * z * sig;
        __nv_bfloat16 hh = __float2bfloat16(o);
        g_yn_h[(size_t)row * DI + idx] = hh;
        g_yn_l[(size_t)row * DI + idx] = __float2bfloat16(o - __bfloat162float(hh));
    }
}

// ---------------- launch -----------------------------------------------------
extern "C" void kernel_launch(void* const* d_in, const int* in_sizes, int n_in,
                              void* d_out, int out_size)
{
    const float* x      = (const float*)d_in[0];
    const float* win    = (const float*)d_in[1];
    const float* convw  = (const float*)d_in[2];
    const float* alog   = (const float*)d_in[3];
    const float* dtb    = (const float*)d_in[4];
    const float* wout   = (const float*)d_in[5];
    float* out = (float*)d_out;

    void *p_proj, *p_xh, *p_xl, *p_winh, *p_winl, *p_wouth, *p_woutl, *p_ynh, *p_ynl;
    cudaGetSymbolAddress(&p_proj,  g_proj);
    cudaGetSymbolAddress(&p_xh,    g_x_h);
    cudaGetSymbolAddress(&p_xl,    g_x_l);
    cudaGetSymbolAddress(&p_winh,  g_win_h);
    cudaGetSymbolAddress(&p_winl,  g_win_l);
    cudaGetSymbolAddress(&p_wouth, g_wout_h);
    cudaGetSymbolAddress(&p_woutl, g_wout_l);
    cudaGetSymbolAddress(&p_ynh,   g_yn_h);
    cudaGetSymbolAddress(&p_ynl,   g_yn_l);

    cudaFuncSetAttribute(ssm_intra, cudaFuncAttributeMaxDynamicSharedMemorySize,
                         (int)SSM_SMEM);
    cudaFuncSetAttribute(gemm_bf16x3, cudaFuncAttributeMaxDynamicSharedMemorySize,
                         GSMEM);

    // 0) split fp32 operands into bf16 hi/lo (win tail rows beyond DPROJ stay zero)
    {
        int n4x = (ROWS * DM) / 4;
        split_bf16_kernel<<<(n4x + 255) / 256, 256>>>(
            x, (__nv_bfloat16*)p_xh, (__nv_bfloat16*)p_xl, n4x);
        int n4w = (DPROJ * DM) / 4;
        split_bf16_kernel<<<(n4w + 255) / 256, 256>>>(
            win, (__nv_bfloat16*)p_winh, (__nv_bfloat16*)p_winl, n4w);
        int n4o = (DM * DI) / 4;
        split_bf16_kernel<<<(n4o + 255) / 256, 256>>>(
            wout, (__nv_bfloat16*)p_wouth, (__nv_bfloat16*)p_woutl, n4o);
    }

    // 1) in_proj: proj[4096, PSTR] = x @ win^T (N padded to 16512 = 129*128)
    {
        dim3 grid(PSTR / GBN, ROWS / GBM);         // (129, 32)
        gemm_bf16x3<<<grid, 256, GSMEM>>>(
            (const __nv_bfloat16*)p_xh,  (const __nv_bfloat16*)p_xl,
            (const __nv_bfloat16*)p_winh,(const __nv_bfloat16*)p_winl,
            (float*)p_proj, ROWS, PSTR, DM);
    }
    // 2) conv + silu
    conv_silu_kernel<<<(ROWS*DI)/256, 256>>>(convw);
    // 3) intra-chunk SSM
    {
        dim3 grid(NH, NC, BB);
        ssm_intra<<<grid, 256, SSM_SMEM>>>(alog, dtb);
    }
    // 4) inter-chunk scan
    scan_chunks<<<BB*NH, 256>>>();
    // 5) y_inter accumulate
    {
        dim3 grid(NH, NC, BB);
        y_inter_kernel<<<grid, 256>>>();
    }
    // 6) RMS norm + gate -> yn hi/lo
    rms_gate_kernel<<<ROWS, 256>>>();
    // 7) out_proj: out[4096,2048] = yn @ wout^T (N = 16*128 exact)
    {
        dim3 grid(DM / GBN, ROWS / GBM);           // (16, 32)
        gemm_bf16x3<<<grid, 256, GSMEM>>>(
            (const __nv_bfloat16*)p_ynh, (const __nv_bfloat16*)p_ynl,
            (const __nv_bfloat16*)p_wouth,(const __nv_bfloat16*)p_woutl,
            out, ROWS, DM, DI);
    }
}

// round 15
// speedup vs baseline: 1.2445x; 1.0084x over previous
#include <cuda_runtime.h>
#include <cuda_bf16.h>
#include <math.h>
#include <stdint.h>

#define BB      2
#define TT      2048
#define DM      2048
#define DI      4096
#define NH      64
#define HD      64
#define DS      64
#define NC      8
#define LL      256
#define DPROJ   16448
#define PSTR    16512          // padded proj row stride = 129*128
#define ROWS    (BB*TT)
#define OFF_Z   0
#define OFF_XC  DI
#define OFF_B   (2*DI)
#define OFF_C   (2*DI + NH*DS)
#define OFF_DT  (2*DI + 2*NH*DS)
#define SCALE_F 0.125f
#define RMS_EPS 1.1920929e-07f

// ---------------- scratch (device globals; no allocation allowed) -------------
__device__ float g_proj[(size_t)ROWS * PSTR];
__device__ float g_xc  [(size_t)ROWS * DI];
__device__ float g_y   [(size_t)ROWS * DI];
__device__ float g_cum [(size_t)BB*NC*NH*LL];
__device__ float g_dA  [(size_t)BB*NC*NH];
__device__ float g_dh  [(size_t)BB*NC*NH*HD*DS];
__device__ float g_st  [(size_t)BB*NC*NH*HD*DS];

__device__ __nv_bfloat16 g_x_h   [(size_t)ROWS * DM];
__device__ __nv_bfloat16 g_x_l   [(size_t)ROWS * DM];
__device__ __nv_bfloat16 g_win_h [(size_t)PSTR * DM];
__device__ __nv_bfloat16 g_win_l [(size_t)PSTR * DM];
__device__ __nv_bfloat16 g_wout_h[(size_t)DM * DI];
__device__ __nv_bfloat16 g_wout_l[(size_t)DM * DI];
__device__ __nv_bfloat16 g_yn_h  [(size_t)ROWS * DI];
__device__ __nv_bfloat16 g_yn_l  [(size_t)ROWS * DI];

// ---------------- fp32 -> bf16 hi/lo split ------------------------------------
__global__ void split_bf16_kernel(const float* __restrict__ src,
                                  __nv_bfloat16* __restrict__ hi,
                                  __nv_bfloat16* __restrict__ lo, int n4)
{
    int i = blockIdx.x * blockDim.x + threadIdx.x;
    if (i >= n4) return;
    float4 v = ((const float4*)src)[i];
    __nv_bfloat16 h0 = __float2bfloat16(v.x);
    __nv_bfloat16 h1 = __float2bfloat16(v.y);
    __nv_bfloat16 h2 = __float2bfloat16(v.z);
    __nv_bfloat16 h3 = __float2bfloat16(v.w);
    __nv_bfloat162 H0; H0.x = h0; H0.y = h1;
    __nv_bfloat162 H1; H1.x = h2; H1.y = h3;
    ((__nv_bfloat162*)hi)[2*i]   = H0;
    ((__nv_bfloat162*)hi)[2*i+1] = H1;
    __nv_bfloat162 L0, L1;
    L0.x = __float2bfloat16(v.x - __bfloat162float(h0));
    L0.y = __float2bfloat16(v.y - __bfloat162float(h1));
    L1.x = __float2bfloat16(v.z - __bfloat162float(h2));
    L1.y = __float2bfloat16(v.w - __bfloat162float(h3));
    ((__nv_bfloat162*)lo)[2*i]   = L0;
    ((__nv_bfloat162*)lo)[2*i+1] = L1;
}

// ---------------- 3x-bf16 tensor-core GEMM (NT) ------------------------------
// Block 128x128x32, 8 warps 4(m)x2(n), warp tile 32x64.
// ldmatrix.x4 fragment loads; cp.async double-buffered staging.
// MMA issue reordered per-product (hh sweep, hl sweep, lh sweep) so each
// accumulator's dependent-reuse distance is 4 instead of 1.
#define GBM 128
#define GBN 128
#define GBK 32
#define ASTB 80                    // smem row stride bytes (40 bf16)
#define TILE_SLOT (128*ASTB)       // bytes per [buf][type] slab = 10240
#define AS_BYTES (4*TILE_SLOT)     // A region: 2 buf x 2 type = 40960
#define GSMEM (2*AS_BYTES)         // 81920 total

#define LDSM_X4(r, addr) \
    asm volatile("ldmatrix.sync.aligned.m8n8.x4.shared.b16 {%0,%1,%2,%3}, [%4];" \
        : "=r"((r)[0]),"=r"((r)[1]),"=r"((r)[2]),"=r"((r)[3]) : "r"(addr))
#define CP_ASYNC16(dst, src) \
    asm volatile("cp.async.cg.shared.global [%0], [%1], 16;" :: "r"(dst), "l"(src))
#define CP_COMMIT() asm volatile("cp.async.commit_group;")
#define CP_WAIT0()  asm volatile("cp.async.wait_group 0;")

__device__ __forceinline__ void mma_bf16(float* d, const uint32_t* a, const uint32_t* b)
{
    asm volatile(
        "mma.sync.aligned.m16n8k16.row.col.f32.bf16.bf16.f32 "
        "{%0,%1,%2,%3}, {%4,%5,%6,%7}, {%8,%9}, {%0,%1,%2,%3};\n"
        : "+f"(d[0]), "+f"(d[1]), "+f"(d[2]), "+f"(d[3])
        : "r"(a[0]), "r"(a[1]), "r"(a[2]), "r"(a[3]), "r"(b[0]), "r"(b[1]));
}

__global__ __launch_bounds__(256, 2) void gemm_bf16x3(
    const __nv_bfloat16* __restrict__ Ah, const __nv_bfloat16* __restrict__ Al,
    const __nv_bfloat16* __restrict__ Bh, const __nv_bfloat16* __restrict__ Bl,
    float* __restrict__ C, int M, int N, int K)
{
    extern __shared__ char gsm[];
    const uint32_t asBase = (uint32_t)__cvta_generic_to_shared(gsm);
    const uint32_t bsBase = asBase + AS_BYTES;

    const int t    = threadIdx.x;
    const int warp = t >> 5;
    const int lane = t & 31;
    const int g    = lane >> 2;
    const int tig  = lane & 3;
    const int bm   = blockIdx.y * GBM;
    const int bn   = blockIdx.x * GBN;
    const int wm   = (warp & 3) << 5;   // 0,32,64,96
    const int wn   = (warp >> 2) << 6;  // 0,64

    float acc[2][8][4];
#pragma unroll
    for (int mt = 0; mt < 2; ++mt)
#pragma unroll
        for (int nt = 0; nt < 8; ++nt)
#pragma unroll
            for (int q = 0; q < 4; ++q) acc[mt][nt][q] = 0.f;

    const int lr  = t >> 2;          // 0..63
    const int lkq = (t & 3) << 3;    // 0,8,16,24 elems
    const uint32_t lkb = (uint32_t)lkq * 2;  // bytes

    const __nv_bfloat16* pAh0 = Ah + (size_t)(bm + lr     ) * K + lkq;
    const __nv_bfloat16* pAh1 = Ah + (size_t)(bm + lr + 64) * K + lkq;
    const __nv_bfloat16* pAl0 = Al + (size_t)(bm + lr     ) * K + lkq;
    const __nv_bfloat16* pAl1 = Al + (size_t)(bm + lr + 64) * K + lkq;
    const __nv_bfloat16* pBh0 = Bh + (size_t)(bn + lr     ) * K + lkq;
    const __nv_bfloat16* pBh1 = Bh + (size_t)(bn + lr + 64) * K + lkq;
    const __nv_bfloat16* pBl0 = Bl + (size_t)(bn + lr     ) * K + lkq;
    const __nv_bfloat16* pBl1 = Bl + (size_t)(bn + lr + 64) * K + lkq;

    // per-lane ldmatrix address offsets (bytes)
    const uint32_t offA = (uint32_t)(((lane & 7) + ((lane >> 3) & 1) * 8) * ASTB
                                     + ((lane >> 4) & 1) * 16);
    const uint32_t offB = (uint32_t)(((lane & 7) + ((lane >> 4) & 1) * 8) * ASTB
                                     + ((lane >> 3) & 1) * 16);

#define STAGE(b, k0) do {                                                        \
    uint32_t ab = asBase + (uint32_t)(b) * 2 * TILE_SLOT;                        \
    uint32_t bb = bsBase + (uint32_t)(b) * 2 * TILE_SLOT;                        \
    CP_ASYNC16(ab + (uint32_t)lr*ASTB + lkb,                pAh0 + (k0));        \
    CP_ASYNC16(ab + (uint32_t)(lr+64)*ASTB + lkb,           pAh1 + (k0));        \
    CP_ASYNC16(ab + TILE_SLOT + (uint32_t)lr*ASTB + lkb,    pAl0 + (k0));        \
    CP_ASYNC16(ab + TILE_SLOT + (uint32_t)(lr+64)*ASTB + lkb, pAl1 + (k0));      \
    CP_ASYNC16(bb + (uint32_t)lr*ASTB + lkb,                pBh0 + (k0));        \
    CP_ASYNC16(bb + (uint32_t)(lr+64)*ASTB + lkb,           pBh1 + (k0));        \
    CP_ASYNC16(bb + TILE_SLOT + (uint32_t)lr*ASTB + lkb,    pBl0 + (k0));        \
    CP_ASYNC16(bb + TILE_SLOT + (uint32_t)(lr+64)*ASTB + lkb, pBl1 + (k0));      \
} while (0)

    STAGE(0, 0);
    CP_COMMIT();
    CP_WAIT0();
    __syncthreads();

    int buf = 0;
    for (int k0 = GBK; k0 <= K; k0 += GBK) {
        const bool more = (k0 < K);
        if (more) { STAGE(buf ^ 1, k0); CP_COMMIT(); }

        const uint32_t abuf = asBase + (uint32_t)buf * 2 * TILE_SLOT;
        const uint32_t bbuf = bsBase + (uint32_t)buf * 2 * TILE_SLOT;
#pragma unroll
        for (int kc = 0; kc < 2; ++kc) {
            const uint32_t kb = (uint32_t)kc * 32;   // bytes
            uint32_t ah[2][4], al[2][4];
#pragma unroll
            for (int mt = 0; mt < 2; ++mt) {
                uint32_t rbase = (uint32_t)(wm + mt * 16) * ASTB + kb;
                LDSM_X4(ah[mt], abuf + rbase + offA);
                LDSM_X4(al[mt], abuf + TILE_SLOT + rbase + offA);
            }
#pragma unroll
            for (int ntp = 0; ntp < 4; ++ntp) {
                uint32_t bh2[4], bl2[4];
                uint32_t nbase = (uint32_t)(wn + ntp * 16) * ASTB + kb;
                LDSM_X4(bh2, bbuf + nbase + offB);
                LDSM_X4(bl2, bbuf + TILE_SLOT + nbase + offB);
                // product sweeps: each accumulator touched once per sweep
                // (reuse distance 4 instead of 1)
#pragma unroll
                for (int j = 0; j < 2; ++j)
#pragma unroll
                    for (int mt = 0; mt < 2; ++mt)
                        mma_bf16(acc[mt][ntp*2 + j], ah[mt], &bh2[2*j]);
#pragma unroll
                for (int j = 0; j < 2; ++j)
#pragma unroll
                    for (int mt = 0; mt < 2; ++mt)
                        mma_bf16(acc[mt][ntp*2 + j], ah[mt], &bl2[2*j]);
#pragma unroll
                for (int j = 0; j < 2; ++j)
#pragma unroll
                    for (int mt = 0; mt < 2; ++mt)
                        mma_bf16(acc[mt][ntp*2 + j], al[mt], &bh2[2*j]);
            }
        }

        if (more) {
            CP_WAIT0();
            __syncthreads();
            buf ^= 1;
        }
    }

#pragma unroll
    for (int mt = 0; mt < 2; ++mt)
#pragma unroll
        for (int nt = 0; nt < 8; ++nt) {
            int m0 = bm + wm + mt * 16 + g;
            int n0 = bn + wn + nt * 8 + tig * 2;
            *(float2*)(C + (size_t)m0 * N + n0)       = make_float2(acc[mt][nt][0], acc[mt][nt][1]);
            *(float2*)(C + (size_t)(m0 + 8) * N + n0) = make_float2(acc[mt][nt][2], acc[mt][nt][3]);
        }
#undef STAGE
}

// ---------------- depthwise causal conv (k=4) + SiLU -------------------------
__global__ void conv_silu_kernel(const float* __restrict__ conv_w)
{
    int idx = blockIdx.x * blockDim.x + threadIdx.x;
    if (idx >= ROWS * DI) return;
    int c   = idx & (DI - 1);
    int row = idx >> 12;
    int tpos = row & (TT - 1);
    float w0 = conv_w[c*4+0], w1 = conv_w[c*4+1], w2 = conv_w[c*4+2], w3 = conv_w[c*4+3];
    float s = 0.f;
    if (tpos >= 3) s += w0 * g_proj[(size_t)(row-3) * PSTR + OFF_XC + c];
    if (tpos >= 2) s += w1 * g_proj[(size_t)(row-2) * PSTR + OFF_XC + c];
    if (tpos >= 1) s += w2 * g_proj[(size_t)(row-1) * PSTR + OFF_XC + c];
    s += w3 * g_proj[(size_t)row * PSTR + OFF_XC + c];
    float sig = 1.f / (1.f + __expf(-s));
    g_xc[idx] = s * sig;
}

// ---------------- intra-chunk SSM: one block per (b, chunk, head) ------------
#define SSM_SMEM (size_t)((2*LL*DS + 3*LL) * sizeof(float))
__global__ __launch_bounds__(256, 1) void ssm_intra(
    const float* __restrict__ A_log, const float* __restrict__ dt_bias)
{
    extern __shared__ float sm[];
    float* B_s   = sm;
    float* xd_s  = sm + LL*DS;
    float* cum_s = sm + 2*LL*DS;
    float* dt_s  = cum_s + LL;
    float* w_s   = dt_s + LL;

    const int h = blockIdx.x, c = blockIdx.y, b = blockIdx.z;
    const int i = threadIdx.x;
    const int row0 = b*TT + c*LL;

    float draw = g_proj[(size_t)(row0 + i) * PSTR + OFF_DT + h] + dt_bias[h];
    float sp   = (draw > 20.f) ? draw : log1pf(expf(draw));
    float dt   = fminf(fmaxf(sp, 1e-4f), 0.5f);
    float a    = -expf(A_log[h]);
    dt_s[i]  = dt;
    cum_s[i] = a * dt;
    __syncthreads();
#pragma unroll
    for (int off = 1; off < LL; off <<= 1) {
        float v = (i >= off) ? cum_s[i - off] : 0.f;
        __syncthreads();
        cum_s[i] += v;
        __syncthreads();
    }
    const float mycum = cum_s[i];

    const size_t boff = (size_t)OFF_B + (size_t)h * DS;
    const size_t xoff = (size_t)h * HD;
    for (int idx = i; idx < LL*DS; idx += 256) {
        int l = idx >> 6, n = idx & 63;
        B_s[idx]  = g_proj[(size_t)(row0 + l) * PSTR + boff + n];
        xd_s[idx] = g_xc[(size_t)(row0 + l) * DI + xoff + n] * dt_s[l];
    }
    float Cr[DS];
    {
        const float* crow = g_proj + (size_t)(row0 + i) * PSTR + OFF_C + h * DS;
#pragma unroll
        for (int n = 0; n < DS; n += 4) {
            float4 v = *(const float4*)(crow + n);
            Cr[n] = v.x; Cr[n+1] = v.y; Cr[n+2] = v.z; Cr[n+3] = v.w;
        }
    }
    __syncthreads();

    float acc[HD];
#pragma unroll
    for (int p = 0; p < HD; ++p) acc[p] = 0.f;

    const int imax = i | 31;
    for (int j = 0; j <= imax; ++j) {
        float s = 0.f;
#pragma unroll
        for (int n = 0; n < DS; n += 4) {
            float4 bv = *(const float4*)&B_s[j*DS + n];
            s += Cr[n]*bv.x + Cr[n+1]*bv.y + Cr[n+2]*bv.z + Cr[n+3]*bv.w;
        }
        float w    = __expf(mycum - cum_s[j]) * SCALE_F;
        float coef = (j <= i) ? s * w : 0.f;
#pragma unroll
        for (int p = 0; p < HD; p += 4) {
            float4 xv = *(const float4*)&xd_s[j*HD + p];
            acc[p]   += coef*xv.x; acc[p+1] += coef*xv.y;
            acc[p+2] += coef*xv.z; acc[p+3] += coef*xv.w;
        }
    }

    float* yrow = g_y + (size_t)(row0 + i) * DI + h * HD;
#pragma unroll
    for (int p = 0; p < HD; p += 4)
        *(float4*)(yrow + p) = make_float4(acc[p], acc[p+1], acc[p+2], acc[p+3]);

    const size_t bch = ((size_t)(b*NC + c) * NH + h);
    g_cum[bch * LL + i] = mycum;
    const float cl = cum_s[LL-1];
    if (i == 0) g_dA[bch] = __expf(cl);
    w_s[i] = __expf(cl - mycum);
    __syncthreads();

    const int p  = i >> 2;
    const int n0 = (i & 3) << 4;
    float dacc[16];
#pragma unroll
    for (int q = 0; q < 16; ++q) dacc[q] = 0.f;
    for (int l = 0; l < LL; ++l) {
        float tmp = w_s[l] * xd_s[l*HD + p];
#pragma unroll
        for (int q = 0; q < 16; q += 4) {
            float4 bv = *(const float4*)&B_s[l*DS + n0 + q];
            dacc[q]   += tmp*bv.x; dacc[q+1] += tmp*bv.y;
            dacc[q+2] += tmp*bv.z; dacc[q+3] += tmp*bv.w;
        }
    }
    float* dst = g_dh + (bch * HD + p) * DS + n0;
#pragma unroll
    for (int q = 0; q < 16; q += 4)
        *(float4*)(dst + q) = make_float4(dacc[q], dacc[q+1], dacc[q+2], dacc[q+3]);
}

// ---------------- sequential inter-chunk scan ---------------------------------
__global__ void scan_chunks()
{
    const int bh = blockIdx.x;
    const int b  = bh >> 6, h = bh & 63;
    const int base = threadIdx.x * 16;
    float st[16];
#pragma unroll
    for (int q = 0; q < 16; ++q) st[q] = 0.f;
    for (int c = 0; c < NC; ++c) {
        const size_t bch = ((size_t)(b*NC + c) * NH + h);
        const size_t off = bch * (HD*DS) + base;
        const float da = g_dA[bch];
#pragma unroll
        for (int q = 0; q < 16; q += 4) {
            float4 d = *(const float4*)(g_dh + off + q);
            *(float4*)(g_st + off + q) = make_float4(st[q], st[q+1], st[q+2], st[q+3]);
            st[q]   = da*st[q]   + d.x;  st[q+1] = da*st[q+1] + d.y;
            st[q+2] = da*st[q+2] + d.z;  st[q+3] = da*st[q+3] + d.w;
        }
    }
}

// ---------------- y_inter ----------------------------------------------------
__global__ __launch_bounds__(256) void y_inter_kernel()
{
    __shared__ float st_s[DS*HD];
    const int h = blockIdx.x, c = blockIdx.y, b = blockIdx.z;
    const int i = threadIdx.x;
    const int row0 = b*TT + c*LL;
    const size_t bch = ((size_t)(b*NC + c) * NH + h);
    const size_t soff = bch * (HD*DS);
    for (int idx = i; idx < HD*DS; idx += 256) {
        int p = idx >> 6, n = idx & 63;
        st_s[n*HD + p] = g_st[soff + idx];
    }
    float Cr[DS];
    {
        const float* crow = g_proj + (size_t)(row0 + i) * PSTR + OFF_C + h * DS;
#pragma unroll
        for (int n = 0; n < DS; n += 4) {
            float4 v = *(const float4*)(crow + n);
            Cr[n] = v.x; Cr[n+1] = v.y; Cr[n+2] = v.z; Cr[n+3] = v.w;
        }
    }
    const float ei = __expf(g_cum[bch * LL + i]) * SCALE_F;
    __syncthreads();

    float acc[HD];
#pragma unroll
    for (int p = 0; p < HD; ++p) acc[p] = 0.f;
#pragma unroll 4
    for (int n = 0; n < DS; ++n) {
        float cn = Cr[n];
#pragma unroll
        for (int p = 0; p < HD; p += 4) {
            float4 sv = *(const float4*)&st_s[n*HD + p];
            acc[p]   += cn*sv.x; acc[p+1] += cn*sv.y;
            acc[p+2] += cn*sv.z; acc[p+3] += cn*sv.w;
        }
    }
    float* yrow = g_y + (size_t)(row0 + i) * DI + h * HD;
#pragma unroll
    for (int p = 0; p < HD; p += 4) {
        float4 v = *(const float4*)(yrow + p);
        v.x += ei*acc[p]; v.y += ei*acc[p+1]; v.z += ei*acc[p+2]; v.w += ei*acc[p+3];
        *(float4*)(yrow + p) = v;
    }
}

// ---------------- RMS norm + SiLU(z) gate -> bf16 hi/lo ----------------------
__global__ void rms_gate_kernel()
{
    const int row = blockIdx.x;
    const int t = threadIdx.x;
    __shared__ float red[256];
    const float* yr = g_y + (size_t)row * DI;
    float ss = 0.f;
    for (int idx = t; idx < DI; idx += 256) { float v = yr[idx]; ss += v*v; }
    red[t] = ss;
    __syncthreads();
    for (int s = 128; s > 0; s >>= 1) {
        if (t < s) red[t] += red[t + s];
        __syncthreads();
    }
    const float r = rsqrtf(red[0] * (1.f/DI) + RMS_EPS);
    const float* zr = g_proj + (size_t)row * PSTR + OFF_Z;
    for (int idx = t; idx < DI; idx += 256) {
        float v = yr[idx] * r;
        float z = zr[idx];
        float sig = 1.f / (1.f + __expf(-z));
        float o = v * z * sig;
        __nv_bfloat16 hh = __float2bfloat16(o);
        g_yn_h[(size_t)row * DI + idx] = hh;
        g_yn_l[(size_t)row * DI + idx] = __float2bfloat16(o - __bfloat162float(hh));
    }
}

// ---------------- launch -----------------------------------------------------
extern "C" void kernel_launch(void* const* d_in, const int* in_sizes, int n_in,
                              void* d_out, int out_size)
{
    const float* x      = (const float*)d_in[0];
    const float* win    = (const float*)d_in[1];
    const float* convw  = (const float*)d_in[2];
    const float* alog   = (const float*)d_in[3];
    const float* dtb    = (const float*)d_in[4];
    const float* wout   = (const float*)d_in[5];
    float* out = (float*)d_out;

    void *p_proj, *p_xh, *p_xl, *p_winh, *p_winl, *p_wouth, *p_woutl, *p_ynh, *p_ynl;
    cudaGetSymbolAddress(&p_proj,  g_proj);
    cudaGetSymbolAddress(&p_xh,    g_x_h);
    cudaGetSymbolAddress(&p_xl,    g_x_l);
    cudaGetSymbolAddress(&p_winh,  g_win_h);
    cudaGetSymbolAddress(&p_winl,  g_win_l);
    cudaGetSymbolAddress(&p_wouth, g_wout_h);
    cudaGetSymbolAddress(&p_woutl, g_wout_l);
    cudaGetSymbolAddress(&p_ynh,   g_yn_h);
    cudaGetSymbolAddress(&p_ynl,   g_yn_l);

    cudaFuncSetAttribute(ssm_intra, cudaFuncAttributeMaxDynamicSharedMemorySize,
                         (int)SSM_SMEM);
    cudaFuncSetAttribute(gemm_bf16x3, cudaFuncAttributeMaxDynamicSharedMemorySize,
                         GSMEM);

    // 0) split fp32 operands into bf16 hi/lo (win tail rows beyond DPROJ stay zero)
    {
        int n4x = (ROWS * DM) / 4;
        split_bf16_kernel<<<(n4x + 255) / 256, 256>>>(
            x, (__nv_bfloat16*)p_xh, (__nv_bfloat16*)p_xl, n4x);
        int n4w = (DPROJ * DM) / 4;
        split_bf16_kernel<<<(n4w + 255) / 256, 256>>>(
            win, (__nv_bfloat16*)p_winh, (__nv_bfloat16*)p_winl, n4w);
        int n4o = (DM * DI) / 4;
        split_bf16_kernel<<<(n4o + 255) / 256, 256>>>(
            wout, (__nv_bfloat16*)p_wouth, (__nv_bfloat16*)p_woutl, n4o);
    }

    // 1) in_proj: proj[4096, PSTR] = x @ win^T (N padded to 16512 = 129*128)
    {
        dim3 grid(PSTR / GBN, ROWS / GBM);         // (129, 32)
        gemm_bf16x3<<<grid, 256, GSMEM>>>(
            (const __nv_bfloat16*)p_xh,  (const __nv_bfloat16*)p_xl,
            (const __nv_bfloat16*)p_winh,(const __nv_bfloat16*)p_winl,
            (float*)p_proj, ROWS, PSTR, DM);
    }
    // 2) conv + silu
    conv_silu_kernel<<<(ROWS*DI)/256, 256>>>(convw);
    // 3) intra-chunk SSM
    {
        dim3 grid(NH, NC, BB);
        ssm_intra<<<grid, 256, SSM_SMEM>>>(alog, dtb);
    }
    // 4) inter-chunk scan
    scan_chunks<<<BB*NH, 256>>>();
    // 5) y_inter accumulate
    {
        dim3 grid(NH, NC, BB);
        y_inter_kernel<<<grid, 256>>>();
    }
    // 6) RMS norm + gate -> yn hi/lo
    rms_gate_kernel<<<ROWS, 256>>>();
    // 7) out_proj: out[4096,2048] = yn @ wout^T (N = 16*128 exact)
    {
        dim3 grid(DM / GBN, ROWS / GBM);           // (16, 32)
        gemm_bf16x3<<<grid, 256, GSMEM>>>(
            (const __nv_bfloat16*)p_ynh, (const __nv_bfloat16*)p_ynl,
            (const __nv_bfloat16*)p_wouth,(const __nv_bfloat16*)p_woutl,
            out, ROWS, DM, DI);
    }
}